// round 4
// baseline (speedup 1.0000x reference)
#include <cuda_runtime.h>
#include <cuda_bf16.h>
#include <mma.h>

using namespace nvcuda;

#define NN   50000
#define EE   800000
#define FIN  256
#define HH   8
#define CC   32
#define HC   256   // HH*CC
#define NOUT 40
#define NEG_SLOPE 0.2f
#define NB   ((NN + 255) / 256)   // 196 scan blocks

// ---------------- device scratch ----------------
__device__ __nv_bfloat16 g_h[(size_t)NN * HC];   // 25.6 MB : projected features (bf16)
__device__ float g_act1[(size_t)NN * CC];
__device__ float g_act2[(size_t)NN * CC];
__device__ float g_asrc[NN * HH];
__device__ float g_adst[NN * HH];
__device__ int   g_deg[NN];
__device__ int   g_rowptr[NN + 1];
__device__ int   g_cursor[NN];
__device__ int   g_csr[EE];
__device__ unsigned g_state[NB];   // lookback scan state: value | (flag<<30)

// ---------------- CSR build ----------------
__global__ void zero_kernel() {
    int i = blockIdx.x * blockDim.x + threadIdx.x;
    if (i < NN) g_deg[i] = 0;
    if (i < NB) g_state[i] = 0u;
}

__global__ void count_kernel(const int* __restrict__ ei) {
    int e = blockIdx.x * blockDim.x + threadIdx.x;
    if (e < EE) atomicAdd(&g_deg[ei[EE + e]], 1);
}

// single-pass exclusive scan with decoupled lookback (196 blocks)
__global__ void scan_kernel() {
    __shared__ int sm[256];
    __shared__ int s_prev;
    int b = blockIdx.x, t = threadIdx.x;
    int i = b * 256 + t;
    int v = (i < NN) ? g_deg[i] : 0;
    sm[t] = v;
    __syncthreads();
#pragma unroll
    for (int o = 1; o < 256; o <<= 1) {
        int u = (t >= o) ? sm[t - o] : 0;
        __syncthreads();
        sm[t] += u;
        __syncthreads();
    }
    int blocksum = sm[255];
    if (t == 0) {
        if (b == 0) {
            atomicExch(&g_state[0], (unsigned)blocksum | (2u << 30));
            s_prev = 0;
        } else {
            atomicExch(&g_state[b], (unsigned)blocksum | (1u << 30));
            int prev = 0;
            int j = b - 1;
            while (true) {
                unsigned s = atomicAdd(&g_state[j], 0u);   // atomic read
                unsigned flag = s >> 30;
                if (flag == 2u) { prev += (int)(s & 0x3FFFFFFFu); break; }
                if (flag == 1u) { prev += (int)(s & 0x3FFFFFFFu); --j; }
            }
            atomicExch(&g_state[b], (unsigned)(prev + blocksum) | (2u << 30));
            s_prev = prev;
        }
    }
    __syncthreads();
    int excl = s_prev + sm[t] - v;
    if (i < NN) { g_rowptr[i] = excl; g_cursor[i] = 0; }
    if (i == NN - 1) g_rowptr[NN] = excl + v;
}

__global__ void fill_kernel(const int* __restrict__ ei) {
    int e = blockIdx.x * blockDim.x + threadIdx.x;
    if (e < EE) {
        int src = ei[e];
        int dst = ei[EE + e];
        int pos = atomicAdd(&g_cursor[dst], 1);
        g_csr[g_rowptr[dst] + pos] = src;
    }
}

// ---------------- bf16 tensor-core GEMM ----------------
#define GBM 128
#define GBN 128
#define GBK 32
__global__ __launch_bounds__(256) void gemm_bf16(const float* __restrict__ A,
                                                 const float* __restrict__ B,
                                                 __nv_bfloat16* __restrict__ Cmat,
                                                 int M, int Nc, int K) {
    __shared__ __nv_bfloat16 As[GBM][GBK + 8];
    __shared__ __nv_bfloat16 Bs[GBK][GBN + 8];
    __shared__ float stage[8][16 * 20];

    int tid = threadIdx.x;
    int wid = tid >> 5;
    int lane = tid & 31;
    int wm = wid >> 1;
    int wn = wid & 1;
    int bm = blockIdx.y * GBM;
    int bn = blockIdx.x * GBN;

    wmma::fragment<wmma::accumulator, 16, 16, 16, float> acc[2][4];
#pragma unroll
    for (int i = 0; i < 2; i++)
#pragma unroll
        for (int j = 0; j < 4; j++)
            wmma::fill_fragment(acc[i][j], 0.0f);

    int arow = tid >> 1;
    int acol = (tid & 1) * 16;
    int brow = tid >> 3;
    int bcol = (tid & 7) * 16;

    for (int k0 = 0; k0 < K; k0 += GBK) {
        {
            float4 v[4];
            if (bm + arow < M) {
                const float4* ap = (const float4*)(A + (size_t)(bm + arow) * K + k0 + acol);
#pragma unroll
                for (int t = 0; t < 4; t++) v[t] = ap[t];
            } else {
#pragma unroll
                for (int t = 0; t < 4; t++) v[t] = make_float4(0.f, 0.f, 0.f, 0.f);
            }
            __nv_bfloat16* dstp = &As[arow][acol];
#pragma unroll
            for (int t = 0; t < 4; t++) {
                dstp[4 * t + 0] = __float2bfloat16_rn(v[t].x);
                dstp[4 * t + 1] = __float2bfloat16_rn(v[t].y);
                dstp[4 * t + 2] = __float2bfloat16_rn(v[t].z);
                dstp[4 * t + 3] = __float2bfloat16_rn(v[t].w);
            }
        }
        {
            const float4* bp = (const float4*)(B + (size_t)(k0 + brow) * Nc + bn + bcol);
            __nv_bfloat16* dstp = &Bs[brow][bcol];
#pragma unroll
            for (int t = 0; t < 4; t++) {
                float4 v = bp[t];
                dstp[4 * t + 0] = __float2bfloat16_rn(v.x);
                dstp[4 * t + 1] = __float2bfloat16_rn(v.y);
                dstp[4 * t + 2] = __float2bfloat16_rn(v.z);
                dstp[4 * t + 3] = __float2bfloat16_rn(v.w);
            }
        }
        __syncthreads();
#pragma unroll
        for (int ks = 0; ks < GBK; ks += 16) {
            wmma::fragment<wmma::matrix_a, 16, 16, 16, __nv_bfloat16, wmma::row_major> af[2];
#pragma unroll
            for (int i = 0; i < 2; i++)
                wmma::load_matrix_sync(af[i], &As[wm * 32 + i * 16][ks], GBK + 8);
            wmma::fragment<wmma::matrix_b, 16, 16, 16, __nv_bfloat16, wmma::row_major> bf[4];
#pragma unroll
            for (int j = 0; j < 4; j++)
                wmma::load_matrix_sync(bf[j], &Bs[ks][wn * 64 + j * 16], GBN + 8);
#pragma unroll
            for (int i = 0; i < 2; i++)
#pragma unroll
                for (int j = 0; j < 4; j++)
                    wmma::mma_sync(acc[i][j], af[i], bf[j], acc[i][j]);
        }
        __syncthreads();
    }

    float* st = &stage[wid][0];
    int lr = lane >> 1;
    int lc = (lane & 1) * 8;
#pragma unroll
    for (int i = 0; i < 2; i++) {
#pragma unroll
        for (int j = 0; j < 4; j++) {
            wmma::store_matrix_sync(st, acc[i][j], 20, wmma::mem_row_major);
            __syncwarp();
            int row = bm + wm * 32 + i * 16 + lr;
            int col = bn + wn * 64 + j * 16 + lc;
            if (row < M) {
                __nv_bfloat16 tmp[8];
#pragma unroll
                for (int t = 0; t < 8; t++)
                    tmp[t] = __float2bfloat16_rn(st[lr * 20 + lc + t]);
                *(uint4*)(Cmat + (size_t)row * Nc + col) = *(uint4*)tmp;
            }
            __syncwarp();
        }
    }
}

// ---------------- attention coefficients (bf16 h) ----------------
__global__ void alpha_kernel(const __nv_bfloat16* __restrict__ hbuf,
                             const float* __restrict__ a_src,
                             const float* __restrict__ a_dst) {
    int idx = blockIdx.x * blockDim.x + threadIdx.x;
    if (idx >= NN * HH) return;
    int hd = idx & (HH - 1);
    const __nv_bfloat162* hp = (const __nv_bfloat162*)(hbuf + (size_t)idx * CC);
    const float* as = a_src + hd * CC;
    const float* ad = a_dst + hd * CC;
    float s1 = 0.f, s2 = 0.f;
#pragma unroll
    for (int i = 0; i < 16; i++) {
        float2 v = __bfloat1622float2(hp[i]);
        s1 += v.x * as[2 * i] + v.y * as[2 * i + 1];
        s2 += v.x * ad[2 * i] + v.y * ad[2 * i + 1];
    }
    g_asrc[idx] = s1;
    g_adst[idx] = s2;
}

__device__ __forceinline__ float lrelu(float e) { return e > 0.f ? e : NEG_SLOPE * e; }

// bf16x2 -> 2x f32 by bit-shift (exact widening), accumulate 8 channels
__device__ __forceinline__ void accum8(float* acc, float ex, const uint4& raw) {
    const unsigned* u = (const unsigned*)&raw;
#pragma unroll
    for (int t = 0; t < 4; t++) {
        float lo = __uint_as_float(u[t] << 16);
        float hi = __uint_as_float(u[t] & 0xFFFF0000u);
        acc[2 * t]     += ex * lo;
        acc[2 * t + 1] += ex * hi;
    }
}

// ---------------- single-pass gather aggregation, 4x unrolled ----------------
__global__ __launch_bounds__(256) void aggregate_kernel(const __nv_bfloat16* __restrict__ hbuf,
                                                        const float* __restrict__ asrc,
                                                        const float* __restrict__ adst,
                                                        const float* __restrict__ bias,
                                                        float* __restrict__ outbuf) {
    int w = (blockIdx.x * blockDim.x + threadIdx.x) >> 5;
    int lane = threadIdx.x & 31;
    if (w >= NN) return;
    int dst = w;
    int beg = g_rowptr[dst], end = g_rowptr[dst + 1];
    int hd = lane >> 2;           // head 0..7
    int cb = (lane & 3) * 8;      // channel base within head
    float adst_h = adst[dst * HH + hd];

    float ex_self = __expf(lrelu(asrc[dst * HH + hd] + adst_h));
    float s = ex_self;
    float acc[8] = {0.f, 0.f, 0.f, 0.f, 0.f, 0.f, 0.f, 0.f};
    {
        uint4 raw = *(const uint4*)(hbuf + (size_t)dst * HC + hd * CC + cb);
        accum8(acc, ex_self, raw);
    }

    int i = beg;
    for (; i + 4 <= end; i += 4) {
        int s0 = g_csr[i + 0];
        int s1 = g_csr[i + 1];
        int s2 = g_csr[i + 2];
        int s3 = g_csr[i + 3];
        // batch all gathers up front for MLP
        float a0 = __ldg(asrc + s0 * HH + hd);
        float a1 = __ldg(asrc + s1 * HH + hd);
        float a2 = __ldg(asrc + s2 * HH + hd);
        float a3 = __ldg(asrc + s3 * HH + hd);
        uint4 r0 = *(const uint4*)(hbuf + (size_t)s0 * HC + hd * CC + cb);
        uint4 r1 = *(const uint4*)(hbuf + (size_t)s1 * HC + hd * CC + cb);
        uint4 r2 = *(const uint4*)(hbuf + (size_t)s2 * HC + hd * CC + cb);
        uint4 r3 = *(const uint4*)(hbuf + (size_t)s3 * HC + hd * CC + cb);
        float e0 = __expf(lrelu(a0 + adst_h));
        float e1 = __expf(lrelu(a1 + adst_h));
        float e2 = __expf(lrelu(a2 + adst_h));
        float e3 = __expf(lrelu(a3 + adst_h));
        s += e0 + e1 + e2 + e3;
        accum8(acc, e0, r0);
        accum8(acc, e1, r1);
        accum8(acc, e2, r2);
        accum8(acc, e3, r3);
    }
    for (; i < end; ++i) {
        int src = g_csr[i];
        float a = __ldg(asrc + src * HH + hd);
        uint4 raw = *(const uint4*)(hbuf + (size_t)src * HC + hd * CC + cb);
        float ex = __expf(lrelu(a + adst_h));
        s += ex;
        accum8(acc, ex, raw);
    }

    float inv = 1.f / s;
#pragma unroll
    for (int j = 0; j < 8; j++) acc[j] *= inv;

#pragma unroll
    for (int j = 0; j < 8; j++) {
        float v = acc[j];
        v += __shfl_xor_sync(0xffffffffu, v, 4);
        v += __shfl_xor_sync(0xffffffffu, v, 8);
        v += __shfl_xor_sync(0xffffffffu, v, 16);
        acc[j] = v * 0.125f;
    }

    if (lane < 4) {
        float o[8];
#pragma unroll
        for (int j = 0; j < 8; j++) {
            float v = acc[j] + bias[cb + j];
            o[j] = v > 0.f ? v : (__expf(v) - 1.f);
        }
        float4* op = (float4*)(outbuf + (size_t)dst * CC + cb);
        op[0] = make_float4(o[0], o[1], o[2], o[3]);
        op[1] = make_float4(o[4], o[5], o[6], o[7]);
    }
}

// ---------------- final projection (32->40) + log_softmax ----------------
__global__ __launch_bounds__(128) void final_kernel(const float* __restrict__ act,
                                                    const float* __restrict__ Wo,
                                                    const float* __restrict__ bo,
                                                    float* __restrict__ out) {
    __shared__ float sW[CC * NOUT];
    __shared__ float sb[NOUT];
    for (int i = threadIdx.x; i < CC * NOUT; i += blockDim.x) sW[i] = Wo[i];
    for (int i = threadIdx.x; i < NOUT; i += blockDim.x) sb[i] = bo[i];
    __syncthreads();
    int n = blockIdx.x * blockDim.x + threadIdx.x;
    if (n >= NN) return;
    float xr[CC];
    const float4* ap = (const float4*)(act + (size_t)n * CC);
#pragma unroll
    for (int i = 0; i < 8; i++) {
        float4 v = ap[i];
        xr[4 * i + 0] = v.x; xr[4 * i + 1] = v.y; xr[4 * i + 2] = v.z; xr[4 * i + 3] = v.w;
    }
    float lg[NOUT];
#pragma unroll
    for (int j = 0; j < NOUT; j++) {
        float sum = sb[j];
#pragma unroll
        for (int c = 0; c < CC; c++) sum += xr[c] * sW[c * NOUT + j];
        lg[j] = sum;
    }
    float m = lg[0];
#pragma unroll
    for (int j = 1; j < NOUT; j++) m = fmaxf(m, lg[j]);
    float se = 0.f;
#pragma unroll
    for (int j = 0; j < NOUT; j++) se += __expf(lg[j] - m);
    float lse = m + __logf(se);
    float* op = out + (size_t)n * NOUT;
#pragma unroll
    for (int j = 0; j < NOUT; j++) op[j] = lg[j] - lse;
}

// ---------------- launch ----------------
extern "C" void kernel_launch(void* const* d_in, const int* in_sizes, int n_in,
                              void* d_out, int out_size) {
    const float* x   = (const float*)d_in[0];
    const int*   ei  = (const int*)d_in[1];
    const float* W1  = (const float*)d_in[2];
    const float* as1 = (const float*)d_in[3];
    const float* ad1 = (const float*)d_in[4];
    const float* b1  = (const float*)d_in[5];
    const float* W2  = (const float*)d_in[6];
    const float* as2 = (const float*)d_in[7];
    const float* ad2 = (const float*)d_in[8];
    const float* b2  = (const float*)d_in[9];
    const float* Wo  = (const float*)d_in[10];
    const float* bo  = (const float*)d_in[11];
    float* out = (float*)d_out;

    __nv_bfloat16* hbuf;
    float *act1, *act2, *pasrc, *padst;
    cudaGetSymbolAddress((void**)&hbuf, g_h);
    cudaGetSymbolAddress((void**)&act1, g_act1);
    cudaGetSymbolAddress((void**)&act2, g_act2);
    cudaGetSymbolAddress((void**)&pasrc, g_asrc);
    cudaGetSymbolAddress((void**)&padst, g_adst);

    // CSR build (4 kernels)
    zero_kernel<<<NB, 256>>>();
    count_kernel<<<(EE + 255) / 256, 256>>>(ei);
    scan_kernel<<<NB, 256>>>();
    fill_kernel<<<(EE + 255) / 256, 256>>>(ei);

    dim3 gg(HC / GBN, (NN + GBM - 1) / GBM);

    // ---- layer 1 ----
    gemm_bf16<<<gg, 256>>>(x, W1, hbuf, NN, HC, FIN);
    alpha_kernel<<<(NN * HH + 255) / 256, 256>>>(hbuf, as1, ad1);
    aggregate_kernel<<<(NN * 32 + 255) / 256, 256>>>(hbuf, pasrc, padst, b1, act1);

    // ---- layer 2 ----
    gemm_bf16<<<gg, 256>>>(act1, W2, hbuf, NN, HC, CC);
    alpha_kernel<<<(NN * HH + 255) / 256, 256>>>(hbuf, as2, ad2);
    aggregate_kernel<<<(NN * 32 + 255) / 256, 256>>>(hbuf, pasrc, padst, b2, act2);

    // ---- output head ----
    final_kernel<<<(NN + 127) / 128, 128>>>(act2, Wo, bo, out);
}

// round 5
// speedup vs baseline: 1.5443x; 1.5443x over previous
#include <cuda_runtime.h>
#include <cuda_bf16.h>
#include <mma.h>

using namespace nvcuda;

#define NN   50000
#define EE   800000
#define FIN  256
#define HH   8
#define CC   32
#define HC   256   // HH*CC
#define NOUT 40
#define NEG_SLOPE 0.2f
#define NB   ((NN + 255) / 256)

// ---------------- device scratch ----------------
__device__ __nv_bfloat16 g_h[(size_t)NN * HC];   // 25.6 MB : projected features (bf16)
__device__ float g_act1[(size_t)NN * CC];
__device__ float g_act2[(size_t)NN * CC];
__device__ float g_asrc[NN * HH];
__device__ float g_adst[NN * HH];
__device__ int   g_deg[NN];
__device__ int   g_rowptr[NN + 1];
__device__ int   g_cursor[NN];
__device__ int   g_csr[EE];
__device__ int   g_bsum[NB];
__device__ int   g_boff[NB];

// ---------------- CSR build (round-3 proven path) ----------------
__global__ void zero_kernel() {
    int i = blockIdx.x * blockDim.x + threadIdx.x;
    if (i < NN) g_deg[i] = 0;
}

__global__ void count_kernel(const int* __restrict__ ei) {
    int e = blockIdx.x * blockDim.x + threadIdx.x;
    if (e < EE) atomicAdd(&g_deg[ei[EE + e]], 1);
}

__global__ void degsum_kernel() {
    __shared__ int sm[256];
    int i = blockIdx.x * 256 + threadIdx.x;
    int v = (i < NN) ? g_deg[i] : 0;
    sm[threadIdx.x] = v;
    __syncthreads();
    for (int o = 128; o > 0; o >>= 1) {
        if (threadIdx.x < o) sm[threadIdx.x] += sm[threadIdx.x + o];
        __syncthreads();
    }
    if (threadIdx.x == 0) g_bsum[blockIdx.x] = sm[0];
}

__global__ void scanb_kernel() {
    __shared__ int sm[256];
    int t = threadIdx.x;
    int v = (t < NB) ? g_bsum[t] : 0;
    sm[t] = v;
    __syncthreads();
    for (int o = 1; o < 256; o <<= 1) {
        int u = (t >= o) ? sm[t - o] : 0;
        __syncthreads();
        sm[t] += u;
        __syncthreads();
    }
    if (t < NB) g_boff[t] = sm[t] - v;
}

__global__ void scanc_kernel() {
    __shared__ int sm[256];
    int b = blockIdx.x, t = threadIdx.x;
    int i = b * 256 + t;
    int v = (i < NN) ? g_deg[i] : 0;
    sm[t] = v;
    __syncthreads();
    for (int o = 1; o < 256; o <<= 1) {
        int u = (t >= o) ? sm[t - o] : 0;
        __syncthreads();
        sm[t] += u;
        __syncthreads();
    }
    int excl = g_boff[b] + sm[t] - v;
    if (i < NN) { g_rowptr[i] = excl; g_cursor[i] = 0; }
    if (i == NN - 1) g_rowptr[NN] = excl + v;
}

__global__ void fill_kernel(const int* __restrict__ ei) {
    int e = blockIdx.x * blockDim.x + threadIdx.x;
    if (e < EE) {
        int src = ei[e];
        int dst = ei[EE + e];
        int pos = atomicAdd(&g_cursor[dst], 1);
        g_csr[g_rowptr[dst] + pos] = src;
    }
}

// ---------------- bf16 tensor-core GEMM (round-3 proven) ----------------
#define GBM 128
#define GBN 128
#define GBK 32
__global__ __launch_bounds__(256) void gemm_bf16(const float* __restrict__ A,
                                                 const float* __restrict__ B,
                                                 __nv_bfloat16* __restrict__ Cmat,
                                                 int M, int Nc, int K) {
    __shared__ __nv_bfloat16 As[GBM][GBK + 8];
    __shared__ __nv_bfloat16 Bs[GBK][GBN + 8];
    __shared__ float stage[8][16 * 20];

    int tid = threadIdx.x;
    int wid = tid >> 5;
    int lane = tid & 31;
    int wm = wid >> 1;
    int wn = wid & 1;
    int bm = blockIdx.y * GBM;
    int bn = blockIdx.x * GBN;

    wmma::fragment<wmma::accumulator, 16, 16, 16, float> acc[2][4];
#pragma unroll
    for (int i = 0; i < 2; i++)
#pragma unroll
        for (int j = 0; j < 4; j++)
            wmma::fill_fragment(acc[i][j], 0.0f);

    int arow = tid >> 1;
    int acol = (tid & 1) * 16;
    int brow = tid >> 3;
    int bcol = (tid & 7) * 16;

    for (int k0 = 0; k0 < K; k0 += GBK) {
        {
            float4 v[4];
            if (bm + arow < M) {
                const float4* ap = (const float4*)(A + (size_t)(bm + arow) * K + k0 + acol);
#pragma unroll
                for (int t = 0; t < 4; t++) v[t] = ap[t];
            } else {
#pragma unroll
                for (int t = 0; t < 4; t++) v[t] = make_float4(0.f, 0.f, 0.f, 0.f);
            }
            __nv_bfloat16* dstp = &As[arow][acol];
#pragma unroll
            for (int t = 0; t < 4; t++) {
                dstp[4 * t + 0] = __float2bfloat16_rn(v[t].x);
                dstp[4 * t + 1] = __float2bfloat16_rn(v[t].y);
                dstp[4 * t + 2] = __float2bfloat16_rn(v[t].z);
                dstp[4 * t + 3] = __float2bfloat16_rn(v[t].w);
            }
        }
        {
            const float4* bp = (const float4*)(B + (size_t)(k0 + brow) * Nc + bn + bcol);
            __nv_bfloat16* dstp = &Bs[brow][bcol];
#pragma unroll
            for (int t = 0; t < 4; t++) {
                float4 v = bp[t];
                dstp[4 * t + 0] = __float2bfloat16_rn(v.x);
                dstp[4 * t + 1] = __float2bfloat16_rn(v.y);
                dstp[4 * t + 2] = __float2bfloat16_rn(v.z);
                dstp[4 * t + 3] = __float2bfloat16_rn(v.w);
            }
        }
        __syncthreads();
#pragma unroll
        for (int ks = 0; ks < GBK; ks += 16) {
            wmma::fragment<wmma::matrix_a, 16, 16, 16, __nv_bfloat16, wmma::row_major> af[2];
#pragma unroll
            for (int i = 0; i < 2; i++)
                wmma::load_matrix_sync(af[i], &As[wm * 32 + i * 16][ks], GBK + 8);
            wmma::fragment<wmma::matrix_b, 16, 16, 16, __nv_bfloat16, wmma::row_major> bf[4];
#pragma unroll
            for (int j = 0; j < 4; j++)
                wmma::load_matrix_sync(bf[j], &Bs[ks][wn * 64 + j * 16], GBN + 8);
#pragma unroll
            for (int i = 0; i < 2; i++)
#pragma unroll
                for (int j = 0; j < 4; j++)
                    wmma::mma_sync(acc[i][j], af[i], bf[j], acc[i][j]);
        }
        __syncthreads();
    }

    float* st = &stage[wid][0];
    int lr = lane >> 1;
    int lc = (lane & 1) * 8;
#pragma unroll
    for (int i = 0; i < 2; i++) {
#pragma unroll
        for (int j = 0; j < 4; j++) {
            wmma::store_matrix_sync(st, acc[i][j], 20, wmma::mem_row_major);
            __syncwarp();
            int row = bm + wm * 32 + i * 16 + lr;
            int col = bn + wn * 64 + j * 16 + lc;
            if (row < M) {
                __nv_bfloat16 tmp[8];
#pragma unroll
                for (int t = 0; t < 8; t++)
                    tmp[t] = __float2bfloat16_rn(st[lr * 20 + lc + t]);
                *(uint4*)(Cmat + (size_t)row * Nc + col) = *(uint4*)tmp;
            }
            __syncwarp();
        }
    }
}

// ---------------- attention coefficients (bf16 h) ----------------
__global__ void alpha_kernel(const __nv_bfloat16* __restrict__ hbuf,
                             const float* __restrict__ a_src,
                             const float* __restrict__ a_dst) {
    int idx = blockIdx.x * blockDim.x + threadIdx.x;
    if (idx >= NN * HH) return;
    int hd = idx & (HH - 1);
    const __nv_bfloat162* hp = (const __nv_bfloat162*)(hbuf + (size_t)idx * CC);
    const float* as = a_src + hd * CC;
    const float* ad = a_dst + hd * CC;
    float s1 = 0.f, s2 = 0.f;
#pragma unroll
    for (int i = 0; i < 16; i++) {
        float2 v = __bfloat1622float2(hp[i]);
        s1 += v.x * as[2 * i] + v.y * as[2 * i + 1];
        s2 += v.x * ad[2 * i] + v.y * ad[2 * i + 1];
    }
    g_asrc[idx] = s1;
    g_adst[idx] = s2;
}

__device__ __forceinline__ float lrelu(float e) { return e > 0.f ? e : NEG_SLOPE * e; }

// bf16x2 -> 2x f32 by bit-ops (exact widening), accumulate 8 channels
__device__ __forceinline__ void accum8(float* acc, float ex, const uint4& raw) {
    const unsigned* u = (const unsigned*)&raw;
#pragma unroll
    for (int t = 0; t < 4; t++) {
        float lo = __uint_as_float(u[t] << 16);
        float hi = __uint_as_float(u[t] & 0xFFFF0000u);
        acc[2 * t]     += ex * lo;
        acc[2 * t + 1] += ex * hi;
    }
}

// ---------------- single-pass gather aggregation, depth-1 pipeline ----------------
__global__ __launch_bounds__(256) void aggregate_kernel(const __nv_bfloat16* __restrict__ hbuf,
                                                        const float* __restrict__ asrc,
                                                        const float* __restrict__ adst,
                                                        const float* __restrict__ bias,
                                                        float* __restrict__ outbuf) {
    int w = (blockIdx.x * blockDim.x + threadIdx.x) >> 5;
    int lane = threadIdx.x & 31;
    if (w >= NN) return;
    int dst = w;
    int beg = g_rowptr[dst], end = g_rowptr[dst + 1];
    int hd = lane >> 2;           // head 0..7
    int cb = (lane & 3) * 8;      // channel base within head
    float adst_h = adst[dst * HH + hd];

    float ex_self = __expf(lrelu(asrc[dst * HH + hd] + adst_h));
    float s = ex_self;
    float acc[8] = {0.f, 0.f, 0.f, 0.f, 0.f, 0.f, 0.f, 0.f};
    {
        uint4 raw = *(const uint4*)(hbuf + (size_t)dst * HC + hd * CC + cb);
        accum8(acc, ex_self, raw);
    }

    if (beg < end) {
        // prologue: load edge 'beg'
        int src0 = g_csr[beg];
        float a0 = asrc[src0 * HH + hd];
        uint4 r0 = *(const uint4*)(hbuf + (size_t)src0 * HC + hd * CC + cb);
        for (int i = beg + 1; i < end; ++i) {
            // issue next edge's loads before consuming current (depth-1 pipeline)
            int src1 = g_csr[i];
            float a1 = asrc[src1 * HH + hd];
            uint4 r1 = *(const uint4*)(hbuf + (size_t)src1 * HC + hd * CC + cb);
            float ex = __expf(lrelu(a0 + adst_h));
            s += ex;
            accum8(acc, ex, r0);
            a0 = a1; r0 = r1;
        }
        float ex = __expf(lrelu(a0 + adst_h));
        s += ex;
        accum8(acc, ex, r0);
    }

    float inv = 1.f / s;
#pragma unroll
    for (int j = 0; j < 8; j++) acc[j] *= inv;

#pragma unroll
    for (int j = 0; j < 8; j++) {
        float v = acc[j];
        v += __shfl_xor_sync(0xffffffffu, v, 4);
        v += __shfl_xor_sync(0xffffffffu, v, 8);
        v += __shfl_xor_sync(0xffffffffu, v, 16);
        acc[j] = v * 0.125f;
    }

    if (lane < 4) {
        float o[8];
#pragma unroll
        for (int j = 0; j < 8; j++) {
            float v = acc[j] + bias[cb + j];
            o[j] = v > 0.f ? v : (__expf(v) - 1.f);
        }
        float4* op = (float4*)(outbuf + (size_t)dst * CC + cb);
        op[0] = make_float4(o[0], o[1], o[2], o[3]);
        op[1] = make_float4(o[4], o[5], o[6], o[7]);
    }
}

// ---------------- final projection (32->40) + log_softmax ----------------
__global__ __launch_bounds__(128) void final_kernel(const float* __restrict__ act,
                                                    const float* __restrict__ Wo,
                                                    const float* __restrict__ bo,
                                                    float* __restrict__ out) {
    __shared__ float sW[CC * NOUT];
    __shared__ float sb[NOUT];
    for (int i = threadIdx.x; i < CC * NOUT; i += blockDim.x) sW[i] = Wo[i];
    for (int i = threadIdx.x; i < NOUT; i += blockDim.x) sb[i] = bo[i];
    __syncthreads();
    int n = blockIdx.x * blockDim.x + threadIdx.x;
    if (n >= NN) return;
    float xr[CC];
    const float4* ap = (const float4*)(act + (size_t)n * CC);
#pragma unroll
    for (int i = 0; i < 8; i++) {
        float4 v = ap[i];
        xr[4 * i + 0] = v.x; xr[4 * i + 1] = v.y; xr[4 * i + 2] = v.z; xr[4 * i + 3] = v.w;
    }
    float lg[NOUT];
#pragma unroll
    for (int j = 0; j < NOUT; j++) {
        float sum = sb[j];
#pragma unroll
        for (int c = 0; c < CC; c++) sum += xr[c] * sW[c * NOUT + j];
        lg[j] = sum;
    }
    float m = lg[0];
#pragma unroll
    for (int j = 1; j < NOUT; j++) m = fmaxf(m, lg[j]);
    float se = 0.f;
#pragma unroll
    for (int j = 0; j < NOUT; j++) se += __expf(lg[j] - m);
    float lse = m + __logf(se);
    float* op = out + (size_t)n * NOUT;
#pragma unroll
    for (int j = 0; j < NOUT; j++) op[j] = lg[j] - lse;
}

// ---------------- launch ----------------
extern "C" void kernel_launch(void* const* d_in, const int* in_sizes, int n_in,
                              void* d_out, int out_size) {
    const float* x   = (const float*)d_in[0];
    const int*   ei  = (const int*)d_in[1];
    const float* W1  = (const float*)d_in[2];
    const float* as1 = (const float*)d_in[3];
    const float* ad1 = (const float*)d_in[4];
    const float* b1  = (const float*)d_in[5];
    const float* W2  = (const float*)d_in[6];
    const float* as2 = (const float*)d_in[7];
    const float* ad2 = (const float*)d_in[8];
    const float* b2  = (const float*)d_in[9];
    const float* Wo  = (const float*)d_in[10];
    const float* bo  = (const float*)d_in[11];
    float* out = (float*)d_out;

    __nv_bfloat16* hbuf;
    float *act1, *act2, *pasrc, *padst;
    cudaGetSymbolAddress((void**)&hbuf, g_h);
    cudaGetSymbolAddress((void**)&act1, g_act1);
    cudaGetSymbolAddress((void**)&act2, g_act2);
    cudaGetSymbolAddress((void**)&pasrc, g_asrc);
    cudaGetSymbolAddress((void**)&padst, g_adst);

    // CSR build
    zero_kernel<<<NB, 256>>>();
    count_kernel<<<(EE + 255) / 256, 256>>>(ei);
    degsum_kernel<<<NB, 256>>>();
    scanb_kernel<<<1, 256>>>();
    scanc_kernel<<<NB, 256>>>();
    fill_kernel<<<(EE + 255) / 256, 256>>>(ei);

    dim3 gg(HC / GBN, (NN + GBM - 1) / GBM);

    // ---- layer 1 ----
    gemm_bf16<<<gg, 256>>>(x, W1, hbuf, NN, HC, FIN);
    alpha_kernel<<<(NN * HH + 255) / 256, 256>>>(hbuf, as1, ad1);
    aggregate_kernel<<<(NN * 32 + 255) / 256, 256>>>(hbuf, pasrc, padst, b1, act1);

    // ---- layer 2 ----
    gemm_bf16<<<gg, 256>>>(act1, W2, hbuf, NN, HC, CC);
    alpha_kernel<<<(NN * HH + 255) / 256, 256>>>(hbuf, as2, ad2);
    aggregate_kernel<<<(NN * 32 + 255) / 256, 256>>>(hbuf, pasrc, padst, b2, act2);

    // ---- output head ----
    final_kernel<<<(NN + 127) / 128, 128>>>(act2, Wo, bo, out);
}

// round 6
// speedup vs baseline: 1.6441x; 1.0646x over previous
#include <cuda_runtime.h>
#include <cuda_bf16.h>
#include <mma.h>

using namespace nvcuda;

#define NN   50000
#define EE   800000
#define FIN  256
#define HH   8
#define CC   32
#define HC   256   // HH*CC
#define NOUT 40
#define NEG_SLOPE 0.2f
#define NB   ((NN + 255) / 256)

// ---------------- device scratch ----------------
__device__ __nv_bfloat16 g_h[(size_t)NN * HC];   // 25.6 MB : projected features (bf16)
__device__ float g_act1[(size_t)NN * CC];
__device__ float g_act2[(size_t)NN * CC];
__device__ float g_asrc[NN * HH];
__device__ float g_adst[NN * HH];
__device__ int   g_deg[NN];
__device__ int   g_rowptr[NN + 1];
__device__ int   g_cursor[NN];
__device__ int   g_csr[EE];
__device__ int   g_bsum[NB];
__device__ int   g_boff[NB];

// ---------------- CSR build ----------------
__global__ void zero_kernel() {
    int i = blockIdx.x * blockDim.x + threadIdx.x;
    if (i < NN) g_deg[i] = 0;
}

__global__ void count_kernel(const int* __restrict__ ei) {
    int e = blockIdx.x * blockDim.x + threadIdx.x;
    if (e < EE) atomicAdd(&g_deg[ei[EE + e]], 1);
}

__global__ void degsum_kernel() {
    __shared__ int sm[256];
    int i = blockIdx.x * 256 + threadIdx.x;
    int v = (i < NN) ? g_deg[i] : 0;
    sm[threadIdx.x] = v;
    __syncthreads();
    for (int o = 128; o > 0; o >>= 1) {
        if (threadIdx.x < o) sm[threadIdx.x] += sm[threadIdx.x + o];
        __syncthreads();
    }
    if (threadIdx.x == 0) g_bsum[blockIdx.x] = sm[0];
}

__global__ void scanb_kernel() {
    __shared__ int sm[256];
    int t = threadIdx.x;
    int v = (t < NB) ? g_bsum[t] : 0;
    sm[t] = v;
    __syncthreads();
    for (int o = 1; o < 256; o <<= 1) {
        int u = (t >= o) ? sm[t - o] : 0;
        __syncthreads();
        sm[t] += u;
        __syncthreads();
    }
    if (t < NB) g_boff[t] = sm[t] - v;
}

__global__ void scanc_kernel() {
    __shared__ int sm[256];
    int b = blockIdx.x, t = threadIdx.x;
    int i = b * 256 + t;
    int v = (i < NN) ? g_deg[i] : 0;
    sm[t] = v;
    __syncthreads();
    for (int o = 1; o < 256; o <<= 1) {
        int u = (t >= o) ? sm[t - o] : 0;
        __syncthreads();
        sm[t] += u;
        __syncthreads();
    }
    int excl = g_boff[b] + sm[t] - v;
    if (i < NN) { g_rowptr[i] = excl; g_cursor[i] = 0; }
    if (i == NN - 1) g_rowptr[NN] = excl + v;
}

__global__ void fill_kernel(const int* __restrict__ ei) {
    int e = blockIdx.x * blockDim.x + threadIdx.x;
    if (e < EE) {
        int src = ei[e];
        int dst = ei[EE + e];
        int pos = atomicAdd(&g_cursor[dst], 1);
        g_csr[g_rowptr[dst] + pos] = src;
    }
}

// ---------------- bf16 tensor-core GEMM ----------------
#define GBM 128
#define GBN 128
#define GBK 32
__global__ __launch_bounds__(256) void gemm_bf16(const float* __restrict__ A,
                                                 const float* __restrict__ B,
                                                 __nv_bfloat16* __restrict__ Cmat,
                                                 int M, int Nc, int K) {
    __shared__ __nv_bfloat16 As[GBM][GBK + 8];
    __shared__ __nv_bfloat16 Bs[GBK][GBN + 8];
    __shared__ float stage[8][16 * 20];

    int tid = threadIdx.x;
    int wid = tid >> 5;
    int lane = tid & 31;
    int wm = wid >> 1;
    int wn = wid & 1;
    int bm = blockIdx.y * GBM;
    int bn = blockIdx.x * GBN;

    wmma::fragment<wmma::accumulator, 16, 16, 16, float> acc[2][4];
#pragma unroll
    for (int i = 0; i < 2; i++)
#pragma unroll
        for (int j = 0; j < 4; j++)
            wmma::fill_fragment(acc[i][j], 0.0f);

    int arow = tid >> 1;
    int acol = (tid & 1) * 16;
    int brow = tid >> 3;
    int bcol = (tid & 7) * 16;

    for (int k0 = 0; k0 < K; k0 += GBK) {
        {
            float4 v[4];
            if (bm + arow < M) {
                const float4* ap = (const float4*)(A + (size_t)(bm + arow) * K + k0 + acol);
#pragma unroll
                for (int t = 0; t < 4; t++) v[t] = ap[t];
            } else {
#pragma unroll
                for (int t = 0; t < 4; t++) v[t] = make_float4(0.f, 0.f, 0.f, 0.f);
            }
            __nv_bfloat16* dstp = &As[arow][acol];
#pragma unroll
            for (int t = 0; t < 4; t++) {
                dstp[4 * t + 0] = __float2bfloat16_rn(v[t].x);
                dstp[4 * t + 1] = __float2bfloat16_rn(v[t].y);
                dstp[4 * t + 2] = __float2bfloat16_rn(v[t].z);
                dstp[4 * t + 3] = __float2bfloat16_rn(v[t].w);
            }
        }
        {
            const float4* bp = (const float4*)(B + (size_t)(k0 + brow) * Nc + bn + bcol);
            __nv_bfloat16* dstp = &Bs[brow][bcol];
#pragma unroll
            for (int t = 0; t < 4; t++) {
                float4 v = bp[t];
                dstp[4 * t + 0] = __float2bfloat16_rn(v.x);
                dstp[4 * t + 1] = __float2bfloat16_rn(v.y);
                dstp[4 * t + 2] = __float2bfloat16_rn(v.z);
                dstp[4 * t + 3] = __float2bfloat16_rn(v.w);
            }
        }
        __syncthreads();
#pragma unroll
        for (int ks = 0; ks < GBK; ks += 16) {
            wmma::fragment<wmma::matrix_a, 16, 16, 16, __nv_bfloat16, wmma::row_major> af[2];
#pragma unroll
            for (int i = 0; i < 2; i++)
                wmma::load_matrix_sync(af[i], &As[wm * 32 + i * 16][ks], GBK + 8);
            wmma::fragment<wmma::matrix_b, 16, 16, 16, __nv_bfloat16, wmma::row_major> bf[4];
#pragma unroll
            for (int j = 0; j < 4; j++)
                wmma::load_matrix_sync(bf[j], &Bs[ks][wn * 64 + j * 16], GBN + 8);
#pragma unroll
            for (int i = 0; i < 2; i++)
#pragma unroll
                for (int j = 0; j < 4; j++)
                    wmma::mma_sync(acc[i][j], af[i], bf[j], acc[i][j]);
        }
        __syncthreads();
    }

    float* st = &stage[wid][0];
    int lr = lane >> 1;
    int lc = (lane & 1) * 8;
#pragma unroll
    for (int i = 0; i < 2; i++) {
#pragma unroll
        for (int j = 0; j < 4; j++) {
            wmma::store_matrix_sync(st, acc[i][j], 20, wmma::mem_row_major);
            __syncwarp();
            int row = bm + wm * 32 + i * 16 + lr;
            int col = bn + wn * 64 + j * 16 + lc;
            if (row < M) {
                __nv_bfloat16 tmp[8];
#pragma unroll
                for (int t = 0; t < 8; t++)
                    tmp[t] = __float2bfloat16_rn(st[lr * 20 + lc + t]);
                *(uint4*)(Cmat + (size_t)row * Nc + col) = *(uint4*)tmp;
            }
            __syncwarp();
        }
    }
}

// ---------------- attention coefficients (bf16 h) ----------------
__global__ void alpha_kernel(const __nv_bfloat16* __restrict__ hbuf,
                             const float* __restrict__ a_src,
                             const float* __restrict__ a_dst) {
    int idx = blockIdx.x * blockDim.x + threadIdx.x;
    if (idx >= NN * HH) return;
    int hd = idx & (HH - 1);
    const __nv_bfloat162* hp = (const __nv_bfloat162*)(hbuf + (size_t)idx * CC);
    const float* as = a_src + hd * CC;
    const float* ad = a_dst + hd * CC;
    float s1 = 0.f, s2 = 0.f;
#pragma unroll
    for (int i = 0; i < 16; i++) {
        float2 v = __bfloat1622float2(hp[i]);
        s1 += v.x * as[2 * i] + v.y * as[2 * i + 1];
        s2 += v.x * ad[2 * i] + v.y * ad[2 * i + 1];
    }
    g_asrc[idx] = s1;
    g_adst[idx] = s2;
}

__device__ __forceinline__ float lrelu(float e) { return e > 0.f ? e : NEG_SLOPE * e; }

// bf16x2 -> 2x f32 by bit-ops (exact widening), accumulate 8 channels
__device__ __forceinline__ void accum8(float* acc, float ex, const uint4& raw) {
    const unsigned* u = (const unsigned*)&raw;
#pragma unroll
    for (int t = 0; t < 4; t++) {
        float lo = __uint_as_float(u[t] << 16);
        float hi = __uint_as_float(u[t] & 0xFFFF0000u);
        acc[2 * t]     += ex * lo;
        acc[2 * t + 1] += ex * hi;
    }
}

// ---------------- single-pass gather aggregation, depth-1 pipeline ----------------
__global__ __launch_bounds__(256) void aggregate_kernel(const __nv_bfloat16* __restrict__ hbuf,
                                                        const float* __restrict__ asrc,
                                                        const float* __restrict__ adst,
                                                        const float* __restrict__ bias,
                                                        float* __restrict__ outbuf) {
    int w = (blockIdx.x * blockDim.x + threadIdx.x) >> 5;
    int lane = threadIdx.x & 31;
    if (w >= NN) return;
    int dst = w;
    int beg = g_rowptr[dst], end = g_rowptr[dst + 1];
    int hd = lane >> 2;           // head 0..7
    int cb = (lane & 3) * 8;      // channel base within head
    float adst_h = adst[dst * HH + hd];

    float ex_self = __expf(lrelu(asrc[dst * HH + hd] + adst_h));
    float s = ex_self;
    float acc[8] = {0.f, 0.f, 0.f, 0.f, 0.f, 0.f, 0.f, 0.f};
    {
        uint4 raw = *(const uint4*)(hbuf + (size_t)dst * HC + hd * CC + cb);
        accum8(acc, ex_self, raw);
    }

    if (beg < end) {
        int src0 = g_csr[beg];
        float a0 = asrc[src0 * HH + hd];
        uint4 r0 = *(const uint4*)(hbuf + (size_t)src0 * HC + hd * CC + cb);
        for (int i = beg + 1; i < end; ++i) {
            int src1 = g_csr[i];
            float a1 = asrc[src1 * HH + hd];
            uint4 r1 = *(const uint4*)(hbuf + (size_t)src1 * HC + hd * CC + cb);
            float ex = __expf(lrelu(a0 + adst_h));
            s += ex;
            accum8(acc, ex, r0);
            a0 = a1; r0 = r1;
        }
        float ex = __expf(lrelu(a0 + adst_h));
        s += ex;
        accum8(acc, ex, r0);
    }

    float inv = 1.f / s;
#pragma unroll
    for (int j = 0; j < 8; j++) acc[j] *= inv;

#pragma unroll
    for (int j = 0; j < 8; j++) {
        float v = acc[j];
        v += __shfl_xor_sync(0xffffffffu, v, 4);
        v += __shfl_xor_sync(0xffffffffu, v, 8);
        v += __shfl_xor_sync(0xffffffffu, v, 16);
        acc[j] = v * 0.125f;
    }

    if (lane < 4) {
        float o[8];
#pragma unroll
        for (int j = 0; j < 8; j++) {
            float v = acc[j] + bias[cb + j];
            o[j] = v > 0.f ? v : (__expf(v) - 1.f);
        }
        float4* op = (float4*)(outbuf + (size_t)dst * CC + cb);
        op[0] = make_float4(o[0], o[1], o[2], o[3]);
        op[1] = make_float4(o[4], o[5], o[6], o[7]);
    }
}

// ---------------- final projection (32->40) + log_softmax ----------------
__global__ __launch_bounds__(128) void final_kernel(const float* __restrict__ act,
                                                    const float* __restrict__ Wo,
                                                    const float* __restrict__ bo,
                                                    float* __restrict__ out) {
    __shared__ float sW[CC * NOUT];
    __shared__ float sb[NOUT];
    for (int i = threadIdx.x; i < CC * NOUT; i += blockDim.x) sW[i] = Wo[i];
    for (int i = threadIdx.x; i < NOUT; i += blockDim.x) sb[i] = bo[i];
    __syncthreads();
    int n = blockIdx.x * blockDim.x + threadIdx.x;
    if (n >= NN) return;
    float xr[CC];
    const float4* ap = (const float4*)(act + (size_t)n * CC);
#pragma unroll
    for (int i = 0; i < 8; i++) {
        float4 v = ap[i];
        xr[4 * i + 0] = v.x; xr[4 * i + 1] = v.y; xr[4 * i + 2] = v.z; xr[4 * i + 3] = v.w;
    }
    float lg[NOUT];
#pragma unroll
    for (int j = 0; j < NOUT; j++) {
        float sum = sb[j];
#pragma unroll
        for (int c = 0; c < CC; c++) sum += xr[c] * sW[c * NOUT + j];
        lg[j] = sum;
    }
    float m = lg[0];
#pragma unroll
    for (int j = 1; j < NOUT; j++) m = fmaxf(m, lg[j]);
    float se = 0.f;
#pragma unroll
    for (int j = 0; j < NOUT; j++) se += __expf(lg[j] - m);
    float lse = m + __logf(se);
    float* op = out + (size_t)n * NOUT;
#pragma unroll
    for (int j = 0; j < NOUT; j++) op[j] = lg[j] - lse;
}

// ---------------- launch ----------------
extern "C" void kernel_launch(void* const* d_in, const int* in_sizes, int n_in,
                              void* d_out, int out_size) {
    const float* x   = (const float*)d_in[0];
    const int*   ei  = (const int*)d_in[1];
    const float* W1  = (const float*)d_in[2];
    const float* as1 = (const float*)d_in[3];
    const float* ad1 = (const float*)d_in[4];
    const float* b1  = (const float*)d_in[5];
    const float* W2  = (const float*)d_in[6];
    const float* as2 = (const float*)d_in[7];
    const float* ad2 = (const float*)d_in[8];
    const float* b2  = (const float*)d_in[9];
    const float* Wo  = (const float*)d_in[10];
    const float* bo  = (const float*)d_in[11];
    float* out = (float*)d_out;

    __nv_bfloat16* hbuf;
    float *act1, *act2, *pasrc, *padst;
    cudaGetSymbolAddress((void**)&hbuf, g_h);
    cudaGetSymbolAddress((void**)&act1, g_act1);
    cudaGetSymbolAddress((void**)&act2, g_act2);
    cudaGetSymbolAddress((void**)&pasrc, g_asrc);
    cudaGetSymbolAddress((void**)&padst, g_adst);

    // one-time host resources for the parallel graph branch (no device memory)
    static cudaStream_t s_side = nullptr;
    static cudaEvent_t e_fork = nullptr, e_join = nullptr;
    if (s_side == nullptr) {
        cudaStreamCreateWithFlags(&s_side, cudaStreamNonBlocking);
        cudaEventCreateWithFlags(&e_fork, cudaEventDisableTiming);
        cudaEventCreateWithFlags(&e_join, cudaEventDisableTiming);
    }

    // ---- fork: GEMM1 + alpha1 (depends only on x,W1,a1) runs parallel to CSR build ----
    cudaEventRecord(e_fork, 0);
    cudaStreamWaitEvent(s_side, e_fork, 0);

    dim3 gg(HC / GBN, (NN + GBM - 1) / GBM);
    gemm_bf16<<<gg, 256, 0, s_side>>>(x, W1, hbuf, NN, HC, FIN);
    alpha_kernel<<<(NN * HH + 255) / 256, 256, 0, s_side>>>(hbuf, as1, ad1);
    cudaEventRecord(e_join, s_side);

    // ---- CSR build on the main stream (depends only on edge_index) ----
    zero_kernel<<<NB, 256>>>();
    count_kernel<<<(EE + 255) / 256, 256>>>(ei);
    degsum_kernel<<<NB, 256>>>();
    scanb_kernel<<<1, 256>>>();
    scanc_kernel<<<NB, 256>>>();
    fill_kernel<<<(EE + 255) / 256, 256>>>(ei);

    // ---- join: aggregate1 needs both branches ----
    cudaStreamWaitEvent(0, e_join, 0);
    aggregate_kernel<<<(NN * 32 + 255) / 256, 256>>>(hbuf, pasrc, padst, b1, act1);

    // ---- layer 2 (serial chain) ----
    gemm_bf16<<<gg, 256>>>(act1, W2, hbuf, NN, HC, CC);
    alpha_kernel<<<(NN * HH + 255) / 256, 256>>>(hbuf, as2, ad2);
    aggregate_kernel<<<(NN * 32 + 255) / 256, 256>>>(hbuf, pasrc, padst, b2, act2);

    // ---- output head ----
    final_kernel<<<(NN + 127) / 128, 128>>>(act2, Wo, bo, out);
}

// round 7
// speedup vs baseline: 1.7702x; 1.0767x over previous
#include <cuda_runtime.h>
#include <cuda_bf16.h>
#include <cuda_fp8.h>
#include <mma.h>

using namespace nvcuda;

#define NN   50000
#define EE   800000
#define FIN  256
#define HH   8
#define CC   32
#define HC   256   // HH*CC
#define NOUT 40
#define NEG_SLOPE 0.2f
#define NB   ((NN + 255) / 256)

// ---------------- device scratch ----------------
__device__ unsigned char g_h[(size_t)NN * HC];   // 12.8 MB : projected features (fp8 e4m3)
__device__ float g_act1[(size_t)NN * CC];
__device__ float g_act2[(size_t)NN * CC];
__device__ float g_asrc[NN * HH];
__device__ float g_adst[NN * HH];
__device__ int   g_deg[NN];
__device__ int   g_rowptr[NN + 1];
__device__ int   g_cursor[NN];
__device__ int   g_csr[EE];
__device__ int   g_bsum[NB];
__device__ int   g_boff[NB];

// fp8x2 -> float2 helper
__device__ __forceinline__ float2 fp8x2_to_float2(unsigned short v) {
    __half2_raw hr = __nv_cvt_fp8x2_to_halfraw2((__nv_fp8x2_storage_t)v, __NV_E4M3);
    return __half22float2(*(__half2*)&hr);
}

// ---------------- CSR build ----------------
__global__ void zero_kernel() {
    int i = blockIdx.x * blockDim.x + threadIdx.x;
    if (i < NN) g_deg[i] = 0;
}

__global__ void count_kernel(const int* __restrict__ ei) {
    int e = blockIdx.x * blockDim.x + threadIdx.x;
    if (e < EE) atomicAdd(&g_deg[ei[EE + e]], 1);
}

__global__ void degsum_kernel() {
    __shared__ int sm[256];
    int i = blockIdx.x * 256 + threadIdx.x;
    int v = (i < NN) ? g_deg[i] : 0;
    sm[threadIdx.x] = v;
    __syncthreads();
    for (int o = 128; o > 0; o >>= 1) {
        if (threadIdx.x < o) sm[threadIdx.x] += sm[threadIdx.x + o];
        __syncthreads();
    }
    if (threadIdx.x == 0) g_bsum[blockIdx.x] = sm[0];
}

__global__ void scanb_kernel() {
    __shared__ int sm[256];
    int t = threadIdx.x;
    int v = (t < NB) ? g_bsum[t] : 0;
    sm[t] = v;
    __syncthreads();
    for (int o = 1; o < 256; o <<= 1) {
        int u = (t >= o) ? sm[t - o] : 0;
        __syncthreads();
        sm[t] += u;
        __syncthreads();
    }
    if (t < NB) g_boff[t] = sm[t] - v;
}

__global__ void scanc_kernel() {
    __shared__ int sm[256];
    int b = blockIdx.x, t = threadIdx.x;
    int i = b * 256 + t;
    int v = (i < NN) ? g_deg[i] : 0;
    sm[t] = v;
    __syncthreads();
    for (int o = 1; o < 256; o <<= 1) {
        int u = (t >= o) ? sm[t - o] : 0;
        __syncthreads();
        sm[t] += u;
        __syncthreads();
    }
    int excl = g_boff[b] + sm[t] - v;
    if (i < NN) { g_rowptr[i] = excl; g_cursor[i] = 0; }
    if (i == NN - 1) g_rowptr[NN] = excl + v;
}

__global__ void fill_kernel(const int* __restrict__ ei) {
    int e = blockIdx.x * blockDim.x + threadIdx.x;
    if (e < EE) {
        int src = ei[e];
        int dst = ei[EE + e];
        int pos = atomicAdd(&g_cursor[dst], 1);
        g_csr[g_rowptr[dst] + pos] = src;
    }
}

// ---------------- bf16 tensor-core GEMM, fp8 output ----------------
#define GBM 128
#define GBN 128
#define GBK 32
__global__ __launch_bounds__(256) void gemm_bf16(const float* __restrict__ A,
                                                 const float* __restrict__ B,
                                                 unsigned char* __restrict__ Cmat,
                                                 int M, int Nc, int K) {
    __shared__ __nv_bfloat16 As[GBM][GBK + 8];
    __shared__ __nv_bfloat16 Bs[GBK][GBN + 8];
    __shared__ float stage[8][16 * 20];

    int tid = threadIdx.x;
    int wid = tid >> 5;
    int lane = tid & 31;
    int wm = wid >> 1;
    int wn = wid & 1;
    int bm = blockIdx.y * GBM;
    int bn = blockIdx.x * GBN;

    wmma::fragment<wmma::accumulator, 16, 16, 16, float> acc[2][4];
#pragma unroll
    for (int i = 0; i < 2; i++)
#pragma unroll
        for (int j = 0; j < 4; j++)
            wmma::fill_fragment(acc[i][j], 0.0f);

    int arow = tid >> 1;
    int acol = (tid & 1) * 16;
    int brow = tid >> 3;
    int bcol = (tid & 7) * 16;

    for (int k0 = 0; k0 < K; k0 += GBK) {
        {
            float4 v[4];
            if (bm + arow < M) {
                const float4* ap = (const float4*)(A + (size_t)(bm + arow) * K + k0 + acol);
#pragma unroll
                for (int t = 0; t < 4; t++) v[t] = ap[t];
            } else {
#pragma unroll
                for (int t = 0; t < 4; t++) v[t] = make_float4(0.f, 0.f, 0.f, 0.f);
            }
            __nv_bfloat16* dstp = &As[arow][acol];
#pragma unroll
            for (int t = 0; t < 4; t++) {
                dstp[4 * t + 0] = __float2bfloat16_rn(v[t].x);
                dstp[4 * t + 1] = __float2bfloat16_rn(v[t].y);
                dstp[4 * t + 2] = __float2bfloat16_rn(v[t].z);
                dstp[4 * t + 3] = __float2bfloat16_rn(v[t].w);
            }
        }
        {
            const float4* bp = (const float4*)(B + (size_t)(k0 + brow) * Nc + bn + bcol);
            __nv_bfloat16* dstp = &Bs[brow][bcol];
#pragma unroll
            for (int t = 0; t < 4; t++) {
                float4 v = bp[t];
                dstp[4 * t + 0] = __float2bfloat16_rn(v.x);
                dstp[4 * t + 1] = __float2bfloat16_rn(v.y);
                dstp[4 * t + 2] = __float2bfloat16_rn(v.z);
                dstp[4 * t + 3] = __float2bfloat16_rn(v.w);
            }
        }
        __syncthreads();
#pragma unroll
        for (int ks = 0; ks < GBK; ks += 16) {
            wmma::fragment<wmma::matrix_a, 16, 16, 16, __nv_bfloat16, wmma::row_major> af[2];
#pragma unroll
            for (int i = 0; i < 2; i++)
                wmma::load_matrix_sync(af[i], &As[wm * 32 + i * 16][ks], GBK + 8);
            wmma::fragment<wmma::matrix_b, 16, 16, 16, __nv_bfloat16, wmma::row_major> bf[4];
#pragma unroll
            for (int j = 0; j < 4; j++)
                wmma::load_matrix_sync(bf[j], &Bs[ks][wn * 64 + j * 16], GBN + 8);
#pragma unroll
            for (int i = 0; i < 2; i++)
#pragma unroll
                for (int j = 0; j < 4; j++)
                    wmma::mma_sync(acc[i][j], af[i], bf[j], acc[i][j]);
        }
        __syncthreads();
    }

    float* st = &stage[wid][0];
    int lr = lane >> 1;
    int lc = (lane & 1) * 8;
#pragma unroll
    for (int i = 0; i < 2; i++) {
#pragma unroll
        for (int j = 0; j < 4; j++) {
            wmma::store_matrix_sync(st, acc[i][j], 20, wmma::mem_row_major);
            __syncwarp();
            int row = bm + wm * 32 + i * 16 + lr;
            int col = bn + wn * 64 + j * 16 + lc;
            if (row < M) {
                unsigned char tmp[8];
#pragma unroll
                for (int t = 0; t < 8; t++)
                    tmp[t] = __nv_cvt_float_to_fp8(st[lr * 20 + lc + t], __NV_SATFINITE, __NV_E4M3);
                *(uint2*)(Cmat + (size_t)row * Nc + col) = *(uint2*)tmp;
            }
            __syncwarp();
        }
    }
}

// ---------------- attention coefficients (fp8 h) ----------------
__global__ void alpha_kernel(const unsigned char* __restrict__ hbuf,
                             const float* __restrict__ a_src,
                             const float* __restrict__ a_dst) {
    int idx = blockIdx.x * blockDim.x + threadIdx.x;
    if (idx >= NN * HH) return;
    int hd = idx & (HH - 1);
    uint4 raw0 = *(const uint4*)(hbuf + (size_t)idx * CC);
    uint4 raw1 = *(const uint4*)(hbuf + (size_t)idx * CC + 16);
    const unsigned short* p0 = (const unsigned short*)&raw0;
    const unsigned short* p1 = (const unsigned short*)&raw1;
    const float* as = a_src + hd * CC;
    const float* ad = a_dst + hd * CC;
    float s1 = 0.f, s2 = 0.f;
#pragma unroll
    for (int i = 0; i < 8; i++) {
        float2 v = fp8x2_to_float2(p0[i]);
        s1 += v.x * as[2 * i] + v.y * as[2 * i + 1];
        s2 += v.x * ad[2 * i] + v.y * ad[2 * i + 1];
    }
#pragma unroll
    for (int i = 0; i < 8; i++) {
        float2 v = fp8x2_to_float2(p1[i]);
        s1 += v.x * as[16 + 2 * i] + v.y * as[16 + 2 * i + 1];
        s2 += v.x * ad[16 + 2 * i] + v.y * ad[16 + 2 * i + 1];
    }
    g_asrc[idx] = s1;
    g_adst[idx] = s2;
}

__device__ __forceinline__ float lrelu(float e) { return e > 0.f ? e : NEG_SLOPE * e; }

// fp8x8 (uint2) -> accumulate 8 channels
__device__ __forceinline__ void accum8(float* acc, float ex, const uint2& raw) {
    const unsigned short* p = (const unsigned short*)&raw;
#pragma unroll
    for (int t = 0; t < 4; t++) {
        float2 v = fp8x2_to_float2(p[t]);
        acc[2 * t]     += ex * v.x;
        acc[2 * t + 1] += ex * v.y;
    }
}

// ---------------- single-pass gather aggregation, depth-1 pipeline (fp8 h) ----------------
__global__ __launch_bounds__(256) void aggregate_kernel(const unsigned char* __restrict__ hbuf,
                                                        const float* __restrict__ asrc,
                                                        const float* __restrict__ adst,
                                                        const float* __restrict__ bias,
                                                        float* __restrict__ outbuf) {
    int w = (blockIdx.x * blockDim.x + threadIdx.x) >> 5;
    int lane = threadIdx.x & 31;
    if (w >= NN) return;
    int dst = w;
    int beg = g_rowptr[dst], end = g_rowptr[dst + 1];
    int hd = lane >> 2;           // head 0..7
    int cb = (lane & 3) * 8;      // channel base within head
    float adst_h = adst[dst * HH + hd];

    float ex_self = __expf(lrelu(asrc[dst * HH + hd] + adst_h));
    float s = ex_self;
    float acc[8] = {0.f, 0.f, 0.f, 0.f, 0.f, 0.f, 0.f, 0.f};
    {
        uint2 raw = *(const uint2*)(hbuf + (size_t)dst * HC + hd * CC + cb);
        accum8(acc, ex_self, raw);
    }

    if (beg < end) {
        int src0 = g_csr[beg];
        float a0 = asrc[src0 * HH + hd];
        uint2 r0 = *(const uint2*)(hbuf + (size_t)src0 * HC + hd * CC + cb);
        for (int i = beg + 1; i < end; ++i) {
            int src1 = g_csr[i];
            float a1 = asrc[src1 * HH + hd];
            uint2 r1 = *(const uint2*)(hbuf + (size_t)src1 * HC + hd * CC + cb);
            float ex = __expf(lrelu(a0 + adst_h));
            s += ex;
            accum8(acc, ex, r0);
            a0 = a1; r0 = r1;
        }
        float ex = __expf(lrelu(a0 + adst_h));
        s += ex;
        accum8(acc, ex, r0);
    }

    float inv = 1.f / s;
#pragma unroll
    for (int j = 0; j < 8; j++) acc[j] *= inv;

#pragma unroll
    for (int j = 0; j < 8; j++) {
        float v = acc[j];
        v += __shfl_xor_sync(0xffffffffu, v, 4);
        v += __shfl_xor_sync(0xffffffffu, v, 8);
        v += __shfl_xor_sync(0xffffffffu, v, 16);
        acc[j] = v * 0.125f;
    }

    if (lane < 4) {
        float o[8];
#pragma unroll
        for (int j = 0; j < 8; j++) {
            float v = acc[j] + bias[cb + j];
            o[j] = v > 0.f ? v : (__expf(v) - 1.f);
        }
        float4* op = (float4*)(outbuf + (size_t)dst * CC + cb);
        op[0] = make_float4(o[0], o[1], o[2], o[3]);
        op[1] = make_float4(o[4], o[5], o[6], o[7]);
    }
}

// ---------------- final projection (32->40) + log_softmax ----------------
__global__ __launch_bounds__(128) void final_kernel(const float* __restrict__ act,
                                                    const float* __restrict__ Wo,
                                                    const float* __restrict__ bo,
                                                    float* __restrict__ out) {
    __shared__ float sW[CC * NOUT];
    __shared__ float sb[NOUT];
    for (int i = threadIdx.x; i < CC * NOUT; i += blockDim.x) sW[i] = Wo[i];
    for (int i = threadIdx.x; i < NOUT; i += blockDim.x) sb[i] = bo[i];
    __syncthreads();
    int n = blockIdx.x * blockDim.x + threadIdx.x;
    if (n >= NN) return;
    float xr[CC];
    const float4* ap = (const float4*)(act + (size_t)n * CC);
#pragma unroll
    for (int i = 0; i < 8; i++) {
        float4 v = ap[i];
        xr[4 * i + 0] = v.x; xr[4 * i + 1] = v.y; xr[4 * i + 2] = v.z; xr[4 * i + 3] = v.w;
    }
    float lg[NOUT];
#pragma unroll
    for (int j = 0; j < NOUT; j++) {
        float sum = sb[j];
#pragma unroll
        for (int c = 0; c < CC; c++) sum += xr[c] * sW[c * NOUT + j];
        lg[j] = sum;
    }
    float m = lg[0];
#pragma unroll
    for (int j = 1; j < NOUT; j++) m = fmaxf(m, lg[j]);
    float se = 0.f;
#pragma unroll
    for (int j = 0; j < NOUT; j++) se += __expf(lg[j] - m);
    float lse = m + __logf(se);
    float* op = out + (size_t)n * NOUT;
#pragma unroll
    for (int j = 0; j < NOUT; j++) op[j] = lg[j] - lse;
}

// ---------------- launch ----------------
extern "C" void kernel_launch(void* const* d_in, const int* in_sizes, int n_in,
                              void* d_out, int out_size) {
    const float* x   = (const float*)d_in[0];
    const int*   ei  = (const int*)d_in[1];
    const float* W1  = (const float*)d_in[2];
    const float* as1 = (const float*)d_in[3];
    const float* ad1 = (const float*)d_in[4];
    const float* b1  = (const float*)d_in[5];
    const float* W2  = (const float*)d_in[6];
    const float* as2 = (const float*)d_in[7];
    const float* ad2 = (const float*)d_in[8];
    const float* b2  = (const float*)d_in[9];
    const float* Wo  = (const float*)d_in[10];
    const float* bo  = (const float*)d_in[11];
    float* out = (float*)d_out;

    unsigned char* hbuf;
    float *act1, *act2, *pasrc, *padst;
    cudaGetSymbolAddress((void**)&hbuf, g_h);
    cudaGetSymbolAddress((void**)&act1, g_act1);
    cudaGetSymbolAddress((void**)&act2, g_act2);
    cudaGetSymbolAddress((void**)&pasrc, g_asrc);
    cudaGetSymbolAddress((void**)&padst, g_adst);

    // one-time host resources for the parallel graph branch (no device memory)
    static cudaStream_t s_side = nullptr;
    static cudaEvent_t e_fork = nullptr, e_join = nullptr;
    if (s_side == nullptr) {
        cudaStreamCreateWithFlags(&s_side, cudaStreamNonBlocking);
        cudaEventCreateWithFlags(&e_fork, cudaEventDisableTiming);
        cudaEventCreateWithFlags(&e_join, cudaEventDisableTiming);
    }

    // ---- fork: GEMM1 + alpha1 parallel to CSR build ----
    cudaEventRecord(e_fork, 0);
    cudaStreamWaitEvent(s_side, e_fork, 0);

    dim3 gg(HC / GBN, (NN + GBM - 1) / GBM);
    gemm_bf16<<<gg, 256, 0, s_side>>>(x, W1, hbuf, NN, HC, FIN);
    alpha_kernel<<<(NN * HH + 255) / 256, 256, 0, s_side>>>(hbuf, as1, ad1);
    cudaEventRecord(e_join, s_side);

    // ---- CSR build on the main stream ----
    zero_kernel<<<NB, 256>>>();
    count_kernel<<<(EE + 255) / 256, 256>>>(ei);
    degsum_kernel<<<NB, 256>>>();
    scanb_kernel<<<1, 256>>>();
    scanc_kernel<<<NB, 256>>>();
    fill_kernel<<<(EE + 255) / 256, 256>>>(ei);

    // ---- join: aggregate1 needs both branches ----
    cudaStreamWaitEvent(0, e_join, 0);
    aggregate_kernel<<<(NN * 32 + 255) / 256, 256>>>(hbuf, pasrc, padst, b1, act1);

    // ---- layer 2 ----
    gemm_bf16<<<gg, 256>>>(act1, W2, hbuf, NN, HC, CC);
    alpha_kernel<<<(NN * HH + 255) / 256, 256>>>(hbuf, as2, ad2);
    aggregate_kernel<<<(NN * 32 + 255) / 256, 256>>>(hbuf, pasrc, padst, b2, act2);

    // ---- output head ----
    final_kernel<<<(NN + 127) / 128, 128>>>(act2, Wo, bo, out);
}